// round 2
// baseline (speedup 1.0000x reference)
#include <cuda_runtime.h>

// TRFAligner: out[d, t] = sum over (seq, k) with sourceIdx[seq] + k == t of TRFs[seq, k, d]
// TRFs: (nSeq, nWin, OUTD) fp32 row-major; out: (OUTD, nRealLen) fp32 row-major.
// sourceIdx sorted ascending -> tile timeline, binary-search overlapping seqs,
// accumulate in REGISTERS (rows statically owned per warp), single smem transpose at end.

#define OUTD      128
#define TILE_T    64
#define ROWPAD    4
#define ROWSTRIDE (OUTD + ROWPAD)     // 132 floats
#define NWARPS    8
#define NTHREADS  (NWARPS * 32)
#define ROWS_PW   (TILE_T / NWARPS)   // 8 rows per warp

__global__ __launch_bounds__(NTHREADS) void trf_fold_kernel(
    const float* __restrict__ TRFs,
    const int*   __restrict__ sIdx,
    float*       __restrict__ out,
    int nSeq, int nWin, int nRealLen)
{
    __shared__ float sm[TILE_T * ROWSTRIDE];

    const int t0      = blockIdx.x * TILE_T;
    const int tEnd    = min(t0 + TILE_T, nRealLen);
    const int tileLen = tEnd - t0;
    const int tid     = threadIdx.x;
    const int w       = tid >> 5;
    const int lane    = tid & 31;

    // ---- binary search seq range overlapping [t0, tEnd): sIdx in [t0-nWin+1, tEnd-1] ----
    int seqLo, seqHi;
    {
        int lo = 0, hi = nSeq, thr = t0 - nWin + 1;
        while (lo < hi) { int m = (lo + hi) >> 1; if (sIdx[m] < thr) lo = m + 1; else hi = m; }
        seqLo = lo;
        hi = nSeq;
        while (lo < hi) { int m = (lo + hi) >> 1; if (sIdx[m] < tEnd) lo = m + 1; else hi = m; }
        seqHi = lo;
    }

    // ---- register accumulation: warp owns rows tt = w + 8*r (static) ----
    float4 acc[ROWS_PW];
    #pragma unroll
    for (int r = 0; r < ROWS_PW; ++r) acc[r] = make_float4(0.f, 0.f, 0.f, 0.f);

    for (int i = seqLo; i < seqHi; ++i) {
        const int s  = sIdx[i];
        const int kb = t0 + w - s;                 // k for row r: kb + 8*r
        const float4* __restrict__ src =
            reinterpret_cast<const float4*>(TRFs + (size_t)i * nWin * OUTD) + lane;
        #pragma unroll
        for (int r = 0; r < ROWS_PW; ++r) {
            const int k = kb + 8 * r;
            if ((unsigned)k < (unsigned)nWin && (w + 8 * r) < tileLen) {
                float4 v = src[k * (OUTD / 4)];    // coalesced 512B row read
                acc[r].x += v.x; acc[r].y += v.y; acc[r].z += v.z; acc[r].w += v.w;
            }
        }
    }

    // ---- one smem pass for the transpose ----
    #pragma unroll
    for (int r = 0; r < ROWS_PW; ++r) {
        const int tt = w + 8 * r;
        *reinterpret_cast<float4*>(sm + tt * ROWSTRIDE + lane * 4) = acc[r];
    }
    __syncthreads();

    // ---- coalesced store: consecutive tid -> consecutive t within each d-row ----
    #pragma unroll
    for (int idx = tid; idx < OUTD * TILE_T; idx += NTHREADS) {
        const int d  = idx >> 6;          // /TILE_T
        const int tt = idx & (TILE_T - 1);
        if (tt < tileLen)
            out[(size_t)d * nRealLen + t0 + tt] = sm[tt * ROWSTRIDE + d];
    }
}

extern "C" void kernel_launch(void* const* d_in, const int* in_sizes, int n_in,
                              void* d_out, int out_size)
{
    const float* TRFs = (const float*)d_in[0];
    const int*   sIdx = (const int*)d_in[1];
    const int nSeq     = in_sizes[1];
    const int nWin     = in_sizes[0] / (nSeq * OUTD);
    const int nRealLen = out_size / OUTD;

    const int grid = (nRealLen + TILE_T - 1) / TILE_T;
    trf_fold_kernel<<<grid, NTHREADS>>>(TRFs, sIdx, (float*)d_out,
                                        nSeq, nWin, nRealLen);
}